// round 13
// baseline (speedup 1.0000x reference)
#include <cuda_runtime.h>
#include <cuda_bf16.h>
#include <cstdint>

#define Bb   8
#define Nn   1024
#define Cc   512
#define Kk   20
#define Mm   64
#define Pp   (Bb * Nn)        // 8192 points
#define CNT1 (Pp * Kk)        // 163840 samples for BN1
#define CNT2 Pp               // 8192 samples for BN2
#define EPS  1e-5f

// Scratch (no cudaMalloc allowed)
__device__ uint32_t g_W1h[128 * 256];   // folded W1' hi, packed bf16 pairs [n][kpair]
__device__ uint32_t g_W1l[128 * 256];   // folded W1' lo
__device__ uint32_t g_W2h[512 * 32];    // W2 hi, packed bf16 pairs [d][mpair]
__device__ uint32_t g_W2l[512 * 32];    // W2 lo
__device__ float g_y[Pp * 128];         // per-point y1(0:64) | y2(64:128)
__device__ float g_hmax[Pp * 64];
__device__ float g_hmin[Pp * 64];
__device__ float g_part1[128 * 256];    // transposed: [col(sum64|sq64)][block 256]
__device__ float g_bn1[128];            // scale(64) | bias(64)
__device__ float g_p2s[512 * 256];      // transposed: [col][ptile 256]
__device__ float g_p2q[512 * 256];
__device__ float g_bn2[1024];           // scale(512) | bias(512)
__device__ int   g_cntB = 0;
__device__ int   g_cntC = 0;

__device__ __forceinline__ void mma_bf16(float* d, const uint32_t* a, const uint32_t* b) {
    asm volatile(
        "mma.sync.aligned.m16n8k16.row.col.f32.bf16.bf16.f32 "
        "{%0,%1,%2,%3}, {%4,%5,%6,%7}, {%8,%9}, {%0,%1,%2,%3};"
        : "+f"(d[0]), "+f"(d[1]), "+f"(d[2]), "+f"(d[3])
        : "r"(a[0]), "r"(a[1]), "r"(a[2]), "r"(a[3]),
          "r"(b[0]), "r"(b[1]));
}

__device__ __forceinline__ uint32_t pack_bf16(float a, float b) {
    __nv_bfloat162 t = __floats2bfloat162_rn(a, b);
    return *reinterpret_cast<uint32_t*>(&t);
}

__device__ __forceinline__ float bf16_round(float v) {
    return __bfloat162float(__float2bfloat16_rn(v));
}

// ---------------------------------------------------------------------------
// k0: prep W1' (fold + bf16 hi/lo pairs) and W2 (bf16 hi/lo pairs). grid=192
// ---------------------------------------------------------------------------
__global__ void k0_prepw(const float* __restrict__ W1, const float* __restrict__ W2) {
    int i = blockIdx.x * 256 + threadIdx.x;      // 0..49151
    if (i < 32768) {
        int n = i >> 8, kp = i & 255;
        int c = kp * 2;
        float v0, v1;
        if (n < 64) {
            float2 a = *reinterpret_cast<const float2*>(&W1[n * 1024 + c]);
            v0 = a.x; v1 = a.y;
        } else {
            int m = n - 64;
            float2 a = *reinterpret_cast<const float2*>(&W1[m * 1024 + c]);
            float2 b = *reinterpret_cast<const float2*>(&W1[m * 1024 + 512 + c]);
            v0 = b.x - a.x; v1 = b.y - a.y;
        }
        float h0 = bf16_round(v0), h1 = bf16_round(v1);
        g_W1h[i] = pack_bf16(v0, v1);
        g_W1l[i] = pack_bf16(v0 - h0, v1 - h1);
    } else {
        int j = i - 32768;                       // 0..16383
        int d = j >> 5, mp = j & 31;
        float2 a = *reinterpret_cast<const float2*>(&W2[d * 64 + mp * 2]);
        float h0 = bf16_round(a.x), h1 = bf16_round(a.y);
        g_W2h[j] = pack_bf16(a.x, a.y);
        g_W2l[j] = pack_bf16(a.x - h0, a.y - h1);
    }
}

// ---------------------------------------------------------------------------
// kA: GEMM1 y = x @ W1'^T, bf16 hi/lo 3-term MMA.
// Tile 64p x 64n, BK=16, 256 thr (8 warps: 4m x 2n, warp = 16p x 32n),
// grid (2,128) = 256 blocks -> ~3 blocks/SM. Double-buffered, reg prefetch.
// ---------------------------------------------------------------------------
__global__ void __launch_bounds__(256) kA_gemm1(const float* __restrict__ x) {
    __shared__ uint32_t sxh[2][64][12], sxl[2][64][12];
    __shared__ uint32_t swh[2][64][12], swl[2][64][12];

    int tid = threadIdx.x;
    int lane = tid & 31, w = tid >> 5;
    int grp = lane >> 2, tig = lane & 3;
    int m_base = (w >> 1) * 16;     // 0,16,32,48
    int n_base = (w & 1) * 32;      // 0,32
    int n0 = blockIdx.x * 64;
    int p0 = blockIdx.y * 64;

    int xrow = tid >> 2;            // 0..63
    int xc = tid & 3;               // float4 seg; pairs 2*xc, 2*xc+1
    int widx = tid & 127;
    int wrow = widx >> 1;           // 0..63
    int whalf = (widx & 1) * 4;     // pair 0 or 4
    const uint32_t* wg = (tid < 128 ? g_W1h : g_W1l) + (n0 + wrow) * 256;
    uint32_t* wsm = (tid < 128) ? &swh[0][0][0] : &swl[0][0][0];

    float acc[4][4];
#pragma unroll
    for (int j = 0; j < 4; j++)
#pragma unroll
        for (int q = 0; q < 4; q++) acc[j][q] = 0.f;

    float4 rx;
    uint4 rw;
    rx = *reinterpret_cast<const float4*>(&x[(p0 + xrow) * 512 + 4 * xc]);
    rw = *reinterpret_cast<const uint4*>(&wg[whalf]);
    {
        float h0 = bf16_round(rx.x), h1 = bf16_round(rx.y);
        float h2 = bf16_round(rx.z), h3 = bf16_round(rx.w);
        sxh[0][xrow][2 * xc]     = pack_bf16(rx.x, rx.y);
        sxh[0][xrow][2 * xc + 1] = pack_bf16(rx.z, rx.w);
        sxl[0][xrow][2 * xc]     = pack_bf16(rx.x - h0, rx.y - h1);
        sxl[0][xrow][2 * xc + 1] = pack_bf16(rx.z - h2, rx.w - h3);
        *reinterpret_cast<uint4*>(wsm + wrow * 12 + whalf) = rw;
    }
    __syncthreads();

    int cur = 0;
    for (int t = 0; t < 32; t++) {
        if (t < 31) {
            int kb = (t + 1) * 16;
            rx = *reinterpret_cast<const float4*>(&x[(p0 + xrow) * 512 + kb + 4 * xc]);
            rw = *reinterpret_cast<const uint4*>(&wg[(t + 1) * 8 + whalf]);
        }
        uint32_t ah[4], al[4], bh[4][2], bl[4][2];
        ah[0] = sxh[cur][m_base + grp][tig];
        ah[1] = sxh[cur][m_base + grp + 8][tig];
        ah[2] = sxh[cur][m_base + grp][4 + tig];
        ah[3] = sxh[cur][m_base + grp + 8][4 + tig];
        al[0] = sxl[cur][m_base + grp][tig];
        al[1] = sxl[cur][m_base + grp + 8][tig];
        al[2] = sxl[cur][m_base + grp][4 + tig];
        al[3] = sxl[cur][m_base + grp + 8][4 + tig];
#pragma unroll
        for (int j = 0; j < 4; j++) {
            int nc = n_base + j * 8 + grp;
            bh[j][0] = swh[cur][nc][tig];
            bh[j][1] = swh[cur][nc][4 + tig];
            bl[j][0] = swl[cur][nc][tig];
            bl[j][1] = swl[cur][nc][4 + tig];
        }
#pragma unroll
        for (int j = 0; j < 4; j++) {
            mma_bf16(acc[j], ah, bh[j]);
            mma_bf16(acc[j], al, bh[j]);
            mma_bf16(acc[j], ah, bl[j]);
        }
        if (t < 31) {
            int nxt = cur ^ 1;
            float h0 = bf16_round(rx.x), h1 = bf16_round(rx.y);
            float h2 = bf16_round(rx.z), h3 = bf16_round(rx.w);
            sxh[nxt][xrow][2 * xc]     = pack_bf16(rx.x, rx.y);
            sxh[nxt][xrow][2 * xc + 1] = pack_bf16(rx.z, rx.w);
            sxl[nxt][xrow][2 * xc]     = pack_bf16(rx.x - h0, rx.y - h1);
            sxl[nxt][xrow][2 * xc + 1] = pack_bf16(rx.z - h2, rx.w - h3);
            *reinterpret_cast<uint4*>(wsm + nxt * 768 + wrow * 12 + whalf) = rw;
            __syncthreads();
            cur = nxt;
        }
    }

    {
        int prow = p0 + m_base + grp;
#pragma unroll
        for (int j = 0; j < 4; j++) {
            int col = n0 + n_base + j * 8 + 2 * tig;
            *reinterpret_cast<float2*>(&g_y[prow * 128 + col]) =
                make_float2(acc[j][0], acc[j][1]);
            *reinterpret_cast<float2*>(&g_y[(prow + 8) * 128 + col]) =
                make_float2(acc[j][2], acc[j][3]);
        }
    }
}

// ---------------------------------------------------------------------------
// kB: gather (max/min + sum/sumsq) + last-block BN1 finalize. grid=256, 256thr
// ---------------------------------------------------------------------------
__global__ void __launch_bounds__(256) kB_gather(const int* __restrict__ idx,
                                                 const float* __restrict__ gamma1,
                                                 const float* __restrict__ beta1) {
    __shared__ int   sidx[640];
    __shared__ float red[2][256];
    __shared__ float tot2[256];
    __shared__ bool  islast;

    int tid = threadIdx.x;
    int pbase = blockIdx.x * 32;
    for (int i = tid; i < 640; i += 256) sidx[i] = idx[pbase * 20 + i];
    __syncthreads();

    int m = tid & 63, slot = tid >> 6;
    float fs = 0.f, fq = 0.f;
#pragma unroll
    for (int i = 0; i < 8; i++) {
        int pl = slot * 8 + i;
        int p = pbase + pl;
        float y2 = g_y[p * 128 + 64 + m];
        int rowb = (p & ~1023) * 128;
        const int* ip = &sidx[pl * 20];
        float vmax = -1e30f, vmin = 1e30f;
#pragma unroll
        for (int k = 0; k < 20; k++) {
            float v = g_y[rowb + ip[k] * 128 + m] + y2;
            fs += v;
            fq += v * v;
            vmax = fmaxf(vmax, v);
            vmin = fminf(vmin, v);
        }
        g_hmax[p * 64 + m] = vmax;
        g_hmin[p * 64 + m] = vmin;
    }
    red[0][tid] = fs;
    red[1][tid] = fq;
    __syncthreads();
    if (tid < 64) {
        float s = red[0][tid] + red[0][tid + 64] + red[0][tid + 128] + red[0][tid + 192];
        float q = red[1][tid] + red[1][tid + 64] + red[1][tid + 128] + red[1][tid + 192];
        g_part1[tid * 256 + blockIdx.x] = s;
        g_part1[(64 + tid) * 256 + blockIdx.x] = q;
    }
    __threadfence();
    __syncthreads();
    if (tid == 0) {
        int old = atomicAdd(&g_cntB, 1);
        islast = (old == 255);
    }
    __syncthreads();
    if (!islast) return;
    __threadfence();

    {
        int col = tid & 127, half = tid >> 7;
        const float4* p4 = reinterpret_cast<const float4*>(&g_part1[col * 256 + half * 128]);
        float s = 0.f;
#pragma unroll 8
        for (int r = 0; r < 32; r++) {
            float4 v = p4[r];
            s += v.x + v.y + v.z + v.w;
        }
        red[0][tid] = s;
    }
    __syncthreads();
    if (tid < 128) tot2[tid] = red[0][tid] + red[0][tid + 128];
    __syncthreads();
    if (tid < 64) {
        float inv = 1.f / (float)CNT1;
        float mu = tot2[tid] * inv;
        float var = tot2[64 + tid] * inv - mu * mu;
        float sc = gamma1[tid] * rsqrtf(var + EPS);
        g_bn1[tid] = sc;
        g_bn1[64 + tid] = beta1[tid] - mu * sc;
        if (tid == 0) g_cntB = 0;
    }
}

// ---------------------------------------------------------------------------
// kC: bf16 GEMM2 + BN2 partial stats + last-block BN2 finalize.
// Tile 32p x 128d, 128 thr (4 warps, one 32-col d-strip each), grid (4,256)
// = 1024 blocks -> ~6 blocks/SM. W2 chunk staged via coalesced uint4
// (double-buffered, reg prefetch). Stores raw h2; kD applies affine.
// ---------------------------------------------------------------------------
__global__ void __launch_bounds__(128) kC_gemm2(const float* __restrict__ gamma2,
                                                const float* __restrict__ beta2,
                                                float* __restrict__ out) {
    __shared__ uint32_t svh[32][36], svl[32][36];         // activations [p][mpair]
    __shared__ uint32_t sbh[2][128][12], sbl[2][128][12]; // W2 chunk [d][kpair]
    __shared__ float sbn[128];
    __shared__ bool  islast;

    int tid = threadIdx.x;
    int lane = tid & 31, w = tid >> 5;          // 4 warps
    int grp = lane >> 2, tig = lane & 3;
    int n_base = w * 32;                        // d-offset per warp
    int d0 = blockIdx.x * 128;
    int p0 = blockIdx.y * 32;

    if (tid < 128) sbn[tid] = g_bn1[tid];
    __syncthreads();

    // stage W2 chunk 0: each thread handles row tid, hi+lo, 2 uint4 each
    uint4 rh0 = *reinterpret_cast<const uint4*>(&g_W2h[(d0 + tid) * 32 + 0]);
    uint4 rh1 = *reinterpret_cast<const uint4*>(&g_W2h[(d0 + tid) * 32 + 4]);
    uint4 rl0 = *reinterpret_cast<const uint4*>(&g_W2l[(d0 + tid) * 32 + 0]);
    uint4 rl1 = *reinterpret_cast<const uint4*>(&g_W2l[(d0 + tid) * 32 + 4]);
    *reinterpret_cast<uint4*>(&sbh[0][tid][0]) = rh0;
    *reinterpret_cast<uint4*>(&sbh[0][tid][4]) = rh1;
    *reinterpret_cast<uint4*>(&sbl[0][tid][0]) = rl0;
    *reinterpret_cast<uint4*>(&sbl[0][tid][4]) = rl1;

    // prologue: activation tile 32 x 32 mpairs = 1024 entries, 8 per thread
#pragma unroll
    for (int i = 0; i < 8; i++) {
        int e = tid + i * 128;
        int pt = e >> 5, mp = e & 31;
        int m0 = 2 * mp;
        float sc0 = sbn[m0], bi0 = sbn[64 + m0];
        float sc1 = sbn[m0 + 1], bi1 = sbn[64 + m0 + 1];
        const float* s0 = (sc0 >= 0.f) ? g_hmax : g_hmin;
        const float* s1 = (sc1 >= 0.f) ? g_hmax : g_hmin;
        float h0 = s0[(p0 + pt) * 64 + m0];
        float h1 = s1[(p0 + pt) * 64 + m0 + 1];
        float v0 = sc0 * h0 + bi0;
        float v1 = sc1 * h1 + bi1;
        v0 = fmaxf(v0, 0.2f * v0);
        v1 = fmaxf(v1, 0.2f * v1);
        float r0 = bf16_round(v0), r1 = bf16_round(v1);
        svh[pt][mp] = pack_bf16(v0, v1);
        svl[pt][mp] = pack_bf16(v0 - r0, v1 - r1);
    }
    __syncthreads();

    float acc[2][4][4];
#pragma unroll
    for (int r = 0; r < 2; r++)
#pragma unroll
        for (int j = 0; j < 4; j++)
#pragma unroll
            for (int q = 0; q < 4; q++) acc[r][j][q] = 0.f;

    int cur = 0;
    for (int ch = 0; ch < 4; ch++) {
        if (ch < 3) {
            int kb = (ch + 1) * 8;
            rh0 = *reinterpret_cast<const uint4*>(&g_W2h[(d0 + tid) * 32 + kb]);
            rh1 = *reinterpret_cast<const uint4*>(&g_W2h[(d0 + tid) * 32 + kb + 4]);
            rl0 = *reinterpret_cast<const uint4*>(&g_W2l[(d0 + tid) * 32 + kb]);
            rl1 = *reinterpret_cast<const uint4*>(&g_W2l[(d0 + tid) * 32 + kb + 4]);
        }
        int kb = ch * 8;
        uint32_t ah[2][4], al[2][4], bh[4][2], bl[4][2];
#pragma unroll
        for (int r = 0; r < 2; r++) {
            int mr = r * 16;
            ah[r][0] = svh[mr + grp][kb + tig];
            ah[r][1] = svh[mr + grp + 8][kb + tig];
            ah[r][2] = svh[mr + grp][kb + 4 + tig];
            ah[r][3] = svh[mr + grp + 8][kb + 4 + tig];
            al[r][0] = svl[mr + grp][kb + tig];
            al[r][1] = svl[mr + grp + 8][kb + tig];
            al[r][2] = svl[mr + grp][kb + 4 + tig];
            al[r][3] = svl[mr + grp + 8][kb + 4 + tig];
        }
#pragma unroll
        for (int j = 0; j < 4; j++) {
            int nc = n_base + j * 8 + grp;
            bh[j][0] = sbh[cur][nc][tig];
            bh[j][1] = sbh[cur][nc][4 + tig];
            bl[j][0] = sbl[cur][nc][tig];
            bl[j][1] = sbl[cur][nc][4 + tig];
        }
#pragma unroll
        for (int r = 0; r < 2; r++)
#pragma unroll
            for (int j = 0; j < 4; j++) {
                mma_bf16(acc[r][j], ah[r], bh[j]);
                mma_bf16(acc[r][j], al[r], bh[j]);
                mma_bf16(acc[r][j], ah[r], bl[j]);
            }
        if (ch < 3) {
            int nxt = cur ^ 1;
            *reinterpret_cast<uint4*>(&sbh[nxt][tid][0]) = rh0;
            *reinterpret_cast<uint4*>(&sbh[nxt][tid][4]) = rh1;
            *reinterpret_cast<uint4*>(&sbl[nxt][tid][0]) = rl0;
            *reinterpret_cast<uint4*>(&sbl[nxt][tid][4]) = rl1;
            __syncthreads();
            cur = nxt;
        }
    }

    // store raw h2 to out
#pragma unroll
    for (int r = 0; r < 2; r++) {
        int prow = p0 + r * 16 + grp;
#pragma unroll
        for (int j = 0; j < 4; j++) {
            int col = d0 + n_base + j * 8 + 2 * tig;
            *reinterpret_cast<float2*>(&out[prow * 512 + col]) =
                make_float2(acc[r][j][0], acc[r][j][1]);
            *reinterpret_cast<float2*>(&out[(prow + 8) * 512 + col]) =
                make_float2(acc[r][j][2], acc[r][j][3]);
        }
    }

    // BN2 partial stats: each warp owns its 32 d-cols fully (all 32 p-rows)
    {
        float ts[8], tq[8];
#pragma unroll
        for (int i = 0; i < 8; i++) { ts[i] = 0.f; tq[i] = 0.f; }
#pragma unroll
        for (int r = 0; r < 2; r++)
#pragma unroll
            for (int j = 0; j < 4; j++)
#pragma unroll
                for (int q = 0; q < 2; q++) {
                    float a0 = acc[r][j][q], a1 = acc[r][j][2 + q];
                    ts[j * 2 + q] += a0 + a1;
                    tq[j * 2 + q] += a0 * a0 + a1 * a1;
                }
#pragma unroll
        for (int i = 0; i < 8; i++) {
#pragma unroll
            for (int off = 4; off < 32; off <<= 1) {
                ts[i] += __shfl_xor_sync(0xffffffffu, ts[i], off);
                tq[i] += __shfl_xor_sync(0xffffffffu, tq[i], off);
            }
        }
        if (lane < 4) {
#pragma unroll
            for (int j = 0; j < 4; j++)
#pragma unroll
                for (int q = 0; q < 2; q++) {
                    int col = d0 + n_base + j * 8 + 2 * lane + q;
                    g_p2s[col * 256 + blockIdx.y] = ts[j * 2 + q];
                    g_p2q[col * 256 + blockIdx.y] = tq[j * 2 + q];
                }
        }
    }

    __threadfence();
    __syncthreads();
    if (tid == 0) {
        int old = atomicAdd(&g_cntC, 1);
        islast = (old == 1023);
    }
    __syncthreads();
    if (!islast) return;
    __threadfence();

    // last block: finalize BN2 (512 cols x 256 partials)
#pragma unroll
    for (int cc = 0; cc < 4; cc++) {
        int col = tid + cc * 128;
        const float4* p4s = reinterpret_cast<const float4*>(&g_p2s[col * 256]);
        const float4* p4q = reinterpret_cast<const float4*>(&g_p2q[col * 256]);
        float s = 0.f, q = 0.f;
#pragma unroll 8
        for (int r = 0; r < 64; r++) {
            float4 a = p4s[r];
            float4 b = p4q[r];
            s += a.x + a.y + a.z + a.w;
            q += b.x + b.y + b.z + b.w;
        }
        float inv = 1.f / (float)CNT2;
        float mu = s * inv;
        float var = q * inv - mu * mu;
        float sc = gamma2[col] * rsqrtf(var + EPS);
        g_bn2[col] = sc;
        g_bn2[512 + col] = beta2[col] - mu * sc;
    }
    if (tid == 0) g_cntC = 0;
}

// ---------------------------------------------------------------------------
// kD: in-place affine + leaky on out. float4 data + float4 bn2 table loads.
// ---------------------------------------------------------------------------
__global__ void __launch_bounds__(512) kD_final(float* __restrict__ out) {
    int i = blockIdx.x * 512 + threadIdx.x;   // float4 index, 1048576 total
    float4 v = reinterpret_cast<float4*>(out)[i];
    int d = (i * 4) & 511;
    float4 sc = *reinterpret_cast<const float4*>(&g_bn2[d]);
    float4 bi = *reinterpret_cast<const float4*>(&g_bn2[512 + d]);
    float t0 = sc.x * v.x + bi.x;
    float t1 = sc.y * v.y + bi.y;
    float t2 = sc.z * v.z + bi.z;
    float t3 = sc.w * v.w + bi.w;
    v.x = fmaxf(t0, 0.2f * t0);
    v.y = fmaxf(t1, 0.2f * t1);
    v.z = fmaxf(t2, 0.2f * t2);
    v.w = fmaxf(t3, 0.2f * t3);
    reinterpret_cast<float4*>(out)[i] = v;
}

// ---------------------------------------------------------------------------
extern "C" void kernel_launch(void* const* d_in, const int* in_sizes, int n_in,
                              void* d_out, int out_size) {
    const float* x      = (const float*)d_in[0];
    const int*   idx    = (const int*)  d_in[1];
    const float* W1     = (const float*)d_in[2];
    const float* gamma1 = (const float*)d_in[3];
    const float* beta1  = (const float*)d_in[4];
    const float* W2     = (const float*)d_in[5];
    const float* gamma2 = (const float*)d_in[6];
    const float* beta2  = (const float*)d_in[7];
    float* out = (float*)d_out;

    k0_prepw<<<192, 256>>>(W1, W2);
    kA_gemm1<<<dim3(2, 128), 256>>>(x);
    kB_gather<<<256, 256>>>(idx, gamma1, beta1);
    kC_gemm2<<<dim3(4, 256), 128>>>(gamma2, beta2, out);
    kD_final<<<2048, 512>>>(out);
}

// round 14
// speedup vs baseline: 1.1739x; 1.1739x over previous
#include <cuda_runtime.h>
#include <cuda_bf16.h>
#include <cstdint>

#define Bb   8
#define Nn   1024
#define Cc   512
#define Kk   20
#define Mm   64
#define Pp   (Bb * Nn)        // 8192 points
#define CNT1 (Pp * Kk)        // 163840 samples for BN1
#define CNT2 Pp               // 8192 samples for BN2
#define EPS  1e-5f

// Scratch (no cudaMalloc allowed)
__device__ uint32_t g_W1h[128 * 256];   // folded W1' hi, packed bf16 pairs [n][kpair]
__device__ uint32_t g_W1l[128 * 256];   // folded W1' lo
__device__ uint32_t g_W2h[512 * 32];    // W2 hi, packed bf16 pairs [d][mpair]
__device__ uint32_t g_W2l[512 * 32];    // W2 lo
__device__ float g_y[Pp * 128];         // per-point y1(0:64) | y2(64:128)
__device__ float g_hmax[Pp * 64];
__device__ float g_hmin[Pp * 64];
__device__ float g_part1[128 * 256];    // transposed: [col(sum64|sq64)][block 256]
__device__ float g_bn1[128];            // scale(64) | bias(64)
__device__ float g_p2s[512 * 128];      // transposed: [col][ptile 128]
__device__ float g_p2q[512 * 128];
__device__ float g_bn2[1024];           // scale(512) | bias(512)
__device__ int   g_cntB = 0;
__device__ int   g_cntD = 0;

__device__ __forceinline__ void mma_bf16(float* d, const uint32_t* a, const uint32_t* b) {
    asm volatile(
        "mma.sync.aligned.m16n8k16.row.col.f32.bf16.bf16.f32 "
        "{%0,%1,%2,%3}, {%4,%5,%6,%7}, {%8,%9}, {%0,%1,%2,%3};"
        : "+f"(d[0]), "+f"(d[1]), "+f"(d[2]), "+f"(d[3])
        : "r"(a[0]), "r"(a[1]), "r"(a[2]), "r"(a[3]),
          "r"(b[0]), "r"(b[1]));
}

__device__ __forceinline__ uint32_t pack_bf16(float a, float b) {
    __nv_bfloat162 t = __floats2bfloat162_rn(a, b);
    return *reinterpret_cast<uint32_t*>(&t);
}

__device__ __forceinline__ float bf16_round(float v) {
    return __bfloat162float(__float2bfloat16_rn(v));
}

// ---------------------------------------------------------------------------
// k0: prep W1' (fold + bf16 hi/lo pairs) and W2 (bf16 hi/lo pairs). grid=192
// ---------------------------------------------------------------------------
__global__ void k0_prepw(const float* __restrict__ W1, const float* __restrict__ W2) {
    int i = blockIdx.x * 256 + threadIdx.x;      // 0..49151
    if (i < 32768) {
        int n = i >> 8, kp = i & 255;
        int c = kp * 2;
        float v0, v1;
        if (n < 64) {
            float2 a = *reinterpret_cast<const float2*>(&W1[n * 1024 + c]);
            v0 = a.x; v1 = a.y;
        } else {
            int m = n - 64;
            float2 a = *reinterpret_cast<const float2*>(&W1[m * 1024 + c]);
            float2 b = *reinterpret_cast<const float2*>(&W1[m * 1024 + 512 + c]);
            v0 = b.x - a.x; v1 = b.y - a.y;
        }
        float h0 = bf16_round(v0), h1 = bf16_round(v1);
        g_W1h[i] = pack_bf16(v0, v1);
        g_W1l[i] = pack_bf16(v0 - h0, v1 - h1);
    } else {
        int j = i - 32768;                       // 0..16383
        int d = j >> 5, mp = j & 31;
        float2 a = *reinterpret_cast<const float2*>(&W2[d * 64 + mp * 2]);
        float h0 = bf16_round(a.x), h1 = bf16_round(a.y);
        g_W2h[j] = pack_bf16(a.x, a.y);
        g_W2l[j] = pack_bf16(a.x - h0, a.y - h1);
    }
}

// ---------------------------------------------------------------------------
// kA: GEMM1 y = x @ W1'^T, bf16 hi/lo 3-term MMA. Tile 64p x 128n, BK=16,
// 512 threads (16 warps: 4m x 4n, warp = 16p x 32n), double-buffered,
// register prefetch, grid=128. Inner loop: pure LDS + MMA.
// ---------------------------------------------------------------------------
__global__ void __launch_bounds__(512) kA_gemm1(const float* __restrict__ x) {
    __shared__ uint32_t sxh[2][64][12], sxl[2][64][12];
    __shared__ uint32_t swh[2][128][12], swl[2][128][12];

    int tid = threadIdx.x;
    int lane = tid & 31, w = tid >> 5;
    int grp = lane >> 2, tig = lane & 3;
    int m_base = (w >> 2) * 16;     // 0,16,32,48
    int n_base = (w & 3) * 32;      // 0,32,64,96
    int p0 = blockIdx.x * 64;

    int xrow = tid >> 3;            // 0..63
    int xp = tid & 7;               // pair index 0..7
    int widx = tid & 255;
    int wrow = widx >> 1;           // 0..127
    int wseg = (widx & 1) * 4;      // pair 0 or 4
    const uint32_t* wg = (tid < 256 ? g_W1h : g_W1l) + wrow * 256;
    uint32_t* wsm = (tid < 256) ? &swh[0][0][0] : &swl[0][0][0];

    float acc[4][4];
#pragma unroll
    for (int j = 0; j < 4; j++)
#pragma unroll
        for (int q = 0; q < 4; q++) acc[j][q] = 0.f;

    float2 rx;
    uint4 rw;
    rx = *reinterpret_cast<const float2*>(&x[(p0 + xrow) * 512 + 2 * xp]);
    rw = *reinterpret_cast<const uint4*>(&wg[wseg]);
    {
        float h0 = bf16_round(rx.x), h1 = bf16_round(rx.y);
        sxh[0][xrow][xp] = pack_bf16(rx.x, rx.y);
        sxl[0][xrow][xp] = pack_bf16(rx.x - h0, rx.y - h1);
        *reinterpret_cast<uint4*>(wsm + wrow * 12 + wseg) = rw;
    }
    __syncthreads();

    int cur = 0;
    for (int t = 0; t < 32; t++) {
        if (t < 31) {
            int kb = (t + 1) * 16;
            rx = *reinterpret_cast<const float2*>(&x[(p0 + xrow) * 512 + kb + 2 * xp]);
            rw = *reinterpret_cast<const uint4*>(&wg[(t + 1) * 8 + wseg]);
        }
        uint32_t ah[4], al[4], bh[4][2], bl[4][2];
        ah[0] = sxh[cur][m_base + grp][tig];
        ah[1] = sxh[cur][m_base + grp + 8][tig];
        ah[2] = sxh[cur][m_base + grp][4 + tig];
        ah[3] = sxh[cur][m_base + grp + 8][4 + tig];
        al[0] = sxl[cur][m_base + grp][tig];
        al[1] = sxl[cur][m_base + grp + 8][tig];
        al[2] = sxl[cur][m_base + grp][4 + tig];
        al[3] = sxl[cur][m_base + grp + 8][4 + tig];
#pragma unroll
        for (int j = 0; j < 4; j++) {
            int nc = n_base + j * 8 + grp;
            bh[j][0] = swh[cur][nc][tig];
            bh[j][1] = swh[cur][nc][4 + tig];
            bl[j][0] = swl[cur][nc][tig];
            bl[j][1] = swl[cur][nc][4 + tig];
        }
#pragma unroll
        for (int j = 0; j < 4; j++) {
            mma_bf16(acc[j], ah, bh[j]);
            mma_bf16(acc[j], al, bh[j]);
            mma_bf16(acc[j], ah, bl[j]);
        }
        if (t < 31) {
            int nxt = cur ^ 1;
            float h0 = bf16_round(rx.x), h1 = bf16_round(rx.y);
            sxh[nxt][xrow][xp] = pack_bf16(rx.x, rx.y);
            sxl[nxt][xrow][xp] = pack_bf16(rx.x - h0, rx.y - h1);
            *reinterpret_cast<uint4*>(wsm + nxt * 1536 + wrow * 12 + wseg) = rw;
            __syncthreads();
            cur = nxt;
        }
    }

    {
        int prow = p0 + m_base + grp;
#pragma unroll
        for (int j = 0; j < 4; j++) {
            int col = n_base + j * 8 + 2 * tig;
            *reinterpret_cast<float2*>(&g_y[prow * 128 + col]) =
                make_float2(acc[j][0], acc[j][1]);
            *reinterpret_cast<float2*>(&g_y[(prow + 8) * 128 + col]) =
                make_float2(acc[j][2], acc[j][3]);
        }
    }
}

// ---------------------------------------------------------------------------
// kB: gather (max/min + sum/sumsq) + last-block BN1 finalize. grid=256, 256thr
// ---------------------------------------------------------------------------
__global__ void __launch_bounds__(256) kB_gather(const int* __restrict__ idx,
                                                 const float* __restrict__ gamma1,
                                                 const float* __restrict__ beta1) {
    __shared__ int   sidx[640];
    __shared__ float red[2][256];
    __shared__ float tot2[256];
    __shared__ bool  islast;

    int tid = threadIdx.x;
    int pbase = blockIdx.x * 32;
    for (int i = tid; i < 640; i += 256) sidx[i] = idx[pbase * 20 + i];
    __syncthreads();

    int m = tid & 63, slot = tid >> 6;
    float fs = 0.f, fq = 0.f;
#pragma unroll
    for (int i = 0; i < 8; i++) {
        int pl = slot * 8 + i;
        int p = pbase + pl;
        float y2 = g_y[p * 128 + 64 + m];
        int rowb = (p & ~1023) * 128;
        const int* ip = &sidx[pl * 20];
        float vmax = -1e30f, vmin = 1e30f;
#pragma unroll
        for (int k = 0; k < 20; k++) {
            float v = g_y[rowb + ip[k] * 128 + m] + y2;
            fs += v;
            fq += v * v;
            vmax = fmaxf(vmax, v);
            vmin = fminf(vmin, v);
        }
        g_hmax[p * 64 + m] = vmax;
        g_hmin[p * 64 + m] = vmin;
    }
    red[0][tid] = fs;
    red[1][tid] = fq;
    __syncthreads();
    if (tid < 64) {
        float s = red[0][tid] + red[0][tid + 64] + red[0][tid + 128] + red[0][tid + 192];
        float q = red[1][tid] + red[1][tid + 64] + red[1][tid + 128] + red[1][tid + 192];
        g_part1[tid * 256 + blockIdx.x] = s;
        g_part1[(64 + tid) * 256 + blockIdx.x] = q;
    }
    __threadfence();
    __syncthreads();
    if (tid == 0) {
        int old = atomicAdd(&g_cntB, 1);
        islast = (old == 255);
    }
    __syncthreads();
    if (!islast) return;
    __threadfence();

    {
        int col = tid & 127, half = tid >> 7;
        const float4* p4 = reinterpret_cast<const float4*>(&g_part1[col * 256 + half * 128]);
        float s = 0.f;
#pragma unroll 8
        for (int r = 0; r < 32; r++) {
            float4 v = p4[r];
            s += v.x + v.y + v.z + v.w;
        }
        red[0][tid] = s;
    }
    __syncthreads();
    if (tid < 128) tot2[tid] = red[0][tid] + red[0][tid + 128];
    __syncthreads();
    if (tid < 64) {
        float inv = 1.f / (float)CNT1;
        float mu = tot2[tid] * inv;
        float var = tot2[64 + tid] * inv - mu * mu;
        float sc = gamma1[tid] * rsqrtf(var + EPS);
        g_bn1[tid] = sc;
        g_bn1[64 + tid] = beta1[tid] - mu * sc;
        if (tid == 0) g_cntB = 0;
    }
}

// ---------------------------------------------------------------------------
// kC: PURE bf16 GEMM2 (no stats, no fences). Tile 64p x 128d, 256 thr,
// grid (4,128). W2 chunks staged via coalesced uint4, double-buffered.
// Stores raw h2 to out.
// ---------------------------------------------------------------------------
__global__ void __launch_bounds__(256) kC_gemm2(float* __restrict__ out) {
    __shared__ uint32_t svh[64][36], svl[64][36];         // activations [p][mpair]
    __shared__ uint32_t sbh[2][128][12], sbl[2][128][12]; // W2 chunk [d][kpair]
    __shared__ float sbn[128];

    int tid = threadIdx.x;
    int lane = tid & 31, w = tid >> 5;
    int grp = lane >> 2, tig = lane & 3;
    int m_base = (w >> 2) * 32;     // p-offset: 0 or 32
    int n_base = (w & 3) * 32;      // d-offset: 0,32,64,96
    int d0 = blockIdx.x * 128;
    int p0 = blockIdx.y * 64;

    int wrow = tid >> 1;            // 0..127
    int whalf = (tid & 1) * 4;      // word 0 or 4

    if (tid < 128) sbn[tid] = g_bn1[tid];
    __syncthreads();

    uint4 rh = *reinterpret_cast<const uint4*>(&g_W2h[(d0 + wrow) * 32 + whalf]);
    uint4 rl = *reinterpret_cast<const uint4*>(&g_W2l[(d0 + wrow) * 32 + whalf]);
    *reinterpret_cast<uint4*>(&sbh[0][wrow][whalf]) = rh;
    *reinterpret_cast<uint4*>(&sbl[0][wrow][whalf]) = rl;

#pragma unroll
    for (int i = 0; i < 8; i++) {
        int e = tid + i * 256;
        int pt = e >> 5, mp = e & 31;
        int m0 = 2 * mp;
        float sc0 = sbn[m0], bi0 = sbn[64 + m0];
        float sc1 = sbn[m0 + 1], bi1 = sbn[64 + m0 + 1];
        const float* s0 = (sc0 >= 0.f) ? g_hmax : g_hmin;
        const float* s1 = (sc1 >= 0.f) ? g_hmax : g_hmin;
        float h0 = s0[(p0 + pt) * 64 + m0];
        float h1 = s1[(p0 + pt) * 64 + m0 + 1];
        float v0 = sc0 * h0 + bi0;
        float v1 = sc1 * h1 + bi1;
        v0 = fmaxf(v0, 0.2f * v0);
        v1 = fmaxf(v1, 0.2f * v1);
        float r0 = bf16_round(v0), r1 = bf16_round(v1);
        svh[pt][mp] = pack_bf16(v0, v1);
        svl[pt][mp] = pack_bf16(v0 - r0, v1 - r1);
    }
    __syncthreads();

    float acc[2][4][4];
#pragma unroll
    for (int r = 0; r < 2; r++)
#pragma unroll
        for (int j = 0; j < 4; j++)
#pragma unroll
            for (int q = 0; q < 4; q++) acc[r][j][q] = 0.f;

    int cur = 0;
    for (int ch = 0; ch < 4; ch++) {
        if (ch < 3) {
            int kb = (ch + 1) * 8;
            rh = *reinterpret_cast<const uint4*>(&g_W2h[(d0 + wrow) * 32 + kb + whalf]);
            rl = *reinterpret_cast<const uint4*>(&g_W2l[(d0 + wrow) * 32 + kb + whalf]);
        }
        int kb = ch * 8;
        uint32_t ah[2][4], al[2][4], bh[4][2], bl[4][2];
#pragma unroll
        for (int r = 0; r < 2; r++) {
            int mr = m_base + r * 16;
            ah[r][0] = svh[mr + grp][kb + tig];
            ah[r][1] = svh[mr + grp + 8][kb + tig];
            ah[r][2] = svh[mr + grp][kb + 4 + tig];
            ah[r][3] = svh[mr + grp + 8][kb + 4 + tig];
            al[r][0] = svl[mr + grp][kb + tig];
            al[r][1] = svl[mr + grp + 8][kb + tig];
            al[r][2] = svl[mr + grp][kb + 4 + tig];
            al[r][3] = svl[mr + grp + 8][kb + 4 + tig];
        }
#pragma unroll
        for (int j = 0; j < 4; j++) {
            int nc = n_base + j * 8 + grp;
            bh[j][0] = sbh[cur][nc][tig];
            bh[j][1] = sbh[cur][nc][4 + tig];
            bl[j][0] = sbl[cur][nc][tig];
            bl[j][1] = sbl[cur][nc][4 + tig];
        }
#pragma unroll
        for (int r = 0; r < 2; r++)
#pragma unroll
            for (int j = 0; j < 4; j++) {
                mma_bf16(acc[r][j], ah[r], bh[j]);
                mma_bf16(acc[r][j], al[r], bh[j]);
                mma_bf16(acc[r][j], ah[r], bl[j]);
            }
        if (ch < 3) {
            int nxt = cur ^ 1;
            *reinterpret_cast<uint4*>(&sbh[nxt][wrow][whalf]) = rh;
            *reinterpret_cast<uint4*>(&sbl[nxt][wrow][whalf]) = rl;
            __syncthreads();
            cur = nxt;
        }
    }

    // store raw h2 to out (no fences, no stats)
#pragma unroll
    for (int r = 0; r < 2; r++) {
        int prow = p0 + m_base + r * 16 + grp;
#pragma unroll
        for (int j = 0; j < 4; j++) {
            int col = d0 + n_base + j * 8 + 2 * tig;
            *reinterpret_cast<float2*>(&out[prow * 512 + col]) =
                make_float2(acc[r][j][0], acc[r][j][1]);
            *reinterpret_cast<float2*>(&out[(prow + 8) * 512 + col]) =
                make_float2(acc[r][j][2], acc[r][j][3]);
        }
    }
}

// ---------------------------------------------------------------------------
// kD1: BN2 stats over out (coalesced) + last-of-64-blocks finalize.
// 64 blocks x 256 thr; block b reduces rows b*128..b*128+127.
// ---------------------------------------------------------------------------
__global__ void __launch_bounds__(256) kD1_stats(const float* __restrict__ out,
                                                 const float* __restrict__ gamma2,
                                                 const float* __restrict__ beta2) {
    __shared__ bool islast;
    int tid = threadIdx.x;
    int col4 = tid & 127;                 // float4 column
    int half = tid >> 7;                  // 0/1
    int r0 = blockIdx.x * 128 + half * 64;
    float s0 = 0.f, s1 = 0.f, s2 = 0.f, s3 = 0.f;
    float q0 = 0.f, q1 = 0.f, q2 = 0.f, q3 = 0.f;
#pragma unroll 4
    for (int rr = 0; rr < 64; rr++) {
        float4 v = *reinterpret_cast<const float4*>(&out[(r0 + rr) * 512 + col4 * 4]);
        s0 += v.x; q0 += v.x * v.x;
        s1 += v.y; q1 += v.y * v.y;
        s2 += v.z; q2 += v.z * v.z;
        s3 += v.w; q3 += v.w * v.w;
    }
    int prow = blockIdx.x * 2 + half;     // 0..127
    int c0 = col4 * 4;
    g_p2s[(c0 + 0) * 128 + prow] = s0;
    g_p2s[(c0 + 1) * 128 + prow] = s1;
    g_p2s[(c0 + 2) * 128 + prow] = s2;
    g_p2s[(c0 + 3) * 128 + prow] = s3;
    g_p2q[(c0 + 0) * 128 + prow] = q0;
    g_p2q[(c0 + 1) * 128 + prow] = q1;
    g_p2q[(c0 + 2) * 128 + prow] = q2;
    g_p2q[(c0 + 3) * 128 + prow] = q3;

    __threadfence();
    __syncthreads();
    if (tid == 0) {
        int old = atomicAdd(&g_cntD, 1);
        islast = (old == 63);
    }
    __syncthreads();
    if (!islast) return;
    __threadfence();

    // finalize: 512 cols x 128 partials; each thread 2 cols
#pragma unroll
    for (int cc = 0; cc < 2; cc++) {
        int col = tid + cc * 256;
        const float4* p4s = reinterpret_cast<const float4*>(&g_p2s[col * 128]);
        const float4* p4q = reinterpret_cast<const float4*>(&g_p2q[col * 128]);
        float s = 0.f, q = 0.f;
#pragma unroll 8
        for (int r = 0; r < 32; r++) {
            float4 a = p4s[r];
            float4 b = p4q[r];
            s += a.x + a.y + a.z + a.w;
            q += b.x + b.y + b.z + b.w;
        }
        float inv = 1.f / (float)CNT2;
        float mu = s * inv;
        float var = q * inv - mu * mu;
        float sc = gamma2[col] * rsqrtf(var + EPS);
        g_bn2[col] = sc;
        g_bn2[512 + col] = beta2[col] - mu * sc;
    }
    if (tid == 0) g_cntD = 0;
}

// ---------------------------------------------------------------------------
// kD2: in-place affine + leaky on out. float4 data + float4 bn2 table loads.
// ---------------------------------------------------------------------------
__global__ void __launch_bounds__(512) kD2_final(float* __restrict__ out) {
    int i = blockIdx.x * 512 + threadIdx.x;   // float4 index, 1048576 total
    float4 v = reinterpret_cast<float4*>(out)[i];
    int d = (i * 4) & 511;
    float4 sc = *reinterpret_cast<const float4*>(&g_bn2[d]);
    float4 bi = *reinterpret_cast<const float4*>(&g_bn2[512 + d]);
    float t0 = sc.x * v.x + bi.x;
    float t1 = sc.y * v.y + bi.y;
    float t2 = sc.z * v.z + bi.z;
    float t3 = sc.w * v.w + bi.w;
    v.x = fmaxf(t0, 0.2f * t0);
    v.y = fmaxf(t1, 0.2f * t1);
    v.z = fmaxf(t2, 0.2f * t2);
    v.w = fmaxf(t3, 0.2f * t3);
    reinterpret_cast<float4*>(out)[i] = v;
}

// ---------------------------------------------------------------------------
extern "C" void kernel_launch(void* const* d_in, const int* in_sizes, int n_in,
                              void* d_out, int out_size) {
    const float* x      = (const float*)d_in[0];
    const int*   idx    = (const int*)  d_in[1];
    const float* W1     = (const float*)d_in[2];
    const float* gamma1 = (const float*)d_in[3];
    const float* beta1  = (const float*)d_in[4];
    const float* W2     = (const float*)d_in[5];
    const float* gamma2 = (const float*)d_in[6];
    const float* beta2  = (const float*)d_in[7];
    float* out = (float*)d_out;

    k0_prepw<<<192, 256>>>(W1, W2);
    kA_gemm1<<<128, 512>>>(x);
    kB_gather<<<256, 256>>>(idx, gamma1, beta1);
    kC_gemm2<<<dim3(4, 128), 256>>>(out);
    kD1_stats<<<64, 256>>>(out, gamma2, beta2);
    kD2_final<<<2048, 512>>>(out);
}

// round 15
// speedup vs baseline: 1.2558x; 1.0698x over previous
#include <cuda_runtime.h>
#include <cuda_bf16.h>
#include <cstdint>

#define Bb   8
#define Nn   1024
#define Cc   512
#define Kk   20
#define Mm   64
#define Pp   (Bb * Nn)        // 8192 points
#define CNT1 (Pp * Kk)        // 163840 samples for BN1
#define CNT2 Pp               // 8192 samples for BN2
#define EPS  1e-5f

// Scratch (no cudaMalloc allowed)
__device__ uint32_t g_W1h[128 * 256];   // folded W1' hi, packed bf16 pairs [n][kpair]
__device__ uint32_t g_W1l[128 * 256];   // folded W1' lo
__device__ uint32_t g_W2h[512 * 32];    // W2 hi, packed bf16 pairs [d][mpair]
__device__ uint32_t g_W2l[512 * 32];    // W2 lo
__device__ float g_y[Pp * 128];         // per-point y1(0:64) | y2(64:128)
__device__ float g_hmax[Pp * 64];
__device__ float g_hmin[Pp * 64];
__device__ float g_part1[128 * 256];    // transposed: [col(sum64|sq64)][block 256]
__device__ float g_bn1[128];            // scale(64) | bias(64)
__device__ float g_p2s[512 * 256];      // transposed: [col][slot 256]
__device__ float g_p2q[512 * 256];
__device__ float g_bn2[1024];           // scale(512) | bias(512)
__device__ int   g_cntB = 0;

__device__ __forceinline__ void mma_bf16(float* d, const uint32_t* a, const uint32_t* b) {
    asm volatile(
        "mma.sync.aligned.m16n8k16.row.col.f32.bf16.bf16.f32 "
        "{%0,%1,%2,%3}, {%4,%5,%6,%7}, {%8,%9}, {%0,%1,%2,%3};"
        : "+f"(d[0]), "+f"(d[1]), "+f"(d[2]), "+f"(d[3])
        : "r"(a[0]), "r"(a[1]), "r"(a[2]), "r"(a[3]),
          "r"(b[0]), "r"(b[1]));
}

__device__ __forceinline__ uint32_t pack_bf16(float a, float b) {
    __nv_bfloat162 t = __floats2bfloat162_rn(a, b);
    return *reinterpret_cast<uint32_t*>(&t);
}

__device__ __forceinline__ float bf16_round(float v) {
    return __bfloat162float(__float2bfloat16_rn(v));
}

// ---------------------------------------------------------------------------
// k0: prep W1' (fold + bf16 hi/lo pairs) and W2 (bf16 hi/lo pairs). grid=192
// ---------------------------------------------------------------------------
__global__ void k0_prepw(const float* __restrict__ W1, const float* __restrict__ W2) {
    int i = blockIdx.x * 256 + threadIdx.x;      // 0..49151
    if (i < 32768) {
        int n = i >> 8, kp = i & 255;
        int c = kp * 2;
        float v0, v1;
        if (n < 64) {
            float2 a = *reinterpret_cast<const float2*>(&W1[n * 1024 + c]);
            v0 = a.x; v1 = a.y;
        } else {
            int m = n - 64;
            float2 a = *reinterpret_cast<const float2*>(&W1[m * 1024 + c]);
            float2 b = *reinterpret_cast<const float2*>(&W1[m * 1024 + 512 + c]);
            v0 = b.x - a.x; v1 = b.y - a.y;
        }
        float h0 = bf16_round(v0), h1 = bf16_round(v1);
        g_W1h[i] = pack_bf16(v0, v1);
        g_W1l[i] = pack_bf16(v0 - h0, v1 - h1);
    } else {
        int j = i - 32768;                       // 0..16383
        int d = j >> 5, mp = j & 31;
        float2 a = *reinterpret_cast<const float2*>(&W2[d * 64 + mp * 2]);
        float h0 = bf16_round(a.x), h1 = bf16_round(a.y);
        g_W2h[j] = pack_bf16(a.x, a.y);
        g_W2l[j] = pack_bf16(a.x - h0, a.y - h1);
    }
}

// ---------------------------------------------------------------------------
// kA: GEMM1 y = x @ W1'^T, bf16 hi/lo 3-term MMA. Tile 64p x 128n, BK=16,
// 512 threads (16 warps: 4m x 4n, warp = 16p x 32n), double-buffered,
// register prefetch, grid=128. Inner loop: pure LDS + MMA.
// ---------------------------------------------------------------------------
__global__ void __launch_bounds__(512) kA_gemm1(const float* __restrict__ x) {
    __shared__ uint32_t sxh[2][64][12], sxl[2][64][12];
    __shared__ uint32_t swh[2][128][12], swl[2][128][12];

    int tid = threadIdx.x;
    int lane = tid & 31, w = tid >> 5;
    int grp = lane >> 2, tig = lane & 3;
    int m_base = (w >> 2) * 16;     // 0,16,32,48
    int n_base = (w & 3) * 32;      // 0,32,64,96
    int p0 = blockIdx.x * 64;

    int xrow = tid >> 3;            // 0..63
    int xp = tid & 7;               // pair index 0..7
    int widx = tid & 255;
    int wrow = widx >> 1;           // 0..127
    int wseg = (widx & 1) * 4;      // pair 0 or 4
    const uint32_t* wg = (tid < 256 ? g_W1h : g_W1l) + wrow * 256;
    uint32_t* wsm = (tid < 256) ? &swh[0][0][0] : &swl[0][0][0];

    float acc[4][4];
#pragma unroll
    for (int j = 0; j < 4; j++)
#pragma unroll
        for (int q = 0; q < 4; q++) acc[j][q] = 0.f;

    float2 rx;
    uint4 rw;
    rx = *reinterpret_cast<const float2*>(&x[(p0 + xrow) * 512 + 2 * xp]);
    rw = *reinterpret_cast<const uint4*>(&wg[wseg]);
    {
        float h0 = bf16_round(rx.x), h1 = bf16_round(rx.y);
        sxh[0][xrow][xp] = pack_bf16(rx.x, rx.y);
        sxl[0][xrow][xp] = pack_bf16(rx.x - h0, rx.y - h1);
        *reinterpret_cast<uint4*>(wsm + wrow * 12 + wseg) = rw;
    }
    __syncthreads();

    int cur = 0;
    for (int t = 0; t < 32; t++) {
        if (t < 31) {
            int kb = (t + 1) * 16;
            rx = *reinterpret_cast<const float2*>(&x[(p0 + xrow) * 512 + kb + 2 * xp]);
            rw = *reinterpret_cast<const uint4*>(&wg[(t + 1) * 8 + wseg]);
        }
        uint32_t ah[4], al[4], bh[4][2], bl[4][2];
        ah[0] = sxh[cur][m_base + grp][tig];
        ah[1] = sxh[cur][m_base + grp + 8][tig];
        ah[2] = sxh[cur][m_base + grp][4 + tig];
        ah[3] = sxh[cur][m_base + grp + 8][4 + tig];
        al[0] = sxl[cur][m_base + grp][tig];
        al[1] = sxl[cur][m_base + grp + 8][tig];
        al[2] = sxl[cur][m_base + grp][4 + tig];
        al[3] = sxl[cur][m_base + grp + 8][4 + tig];
#pragma unroll
        for (int j = 0; j < 4; j++) {
            int nc = n_base + j * 8 + grp;
            bh[j][0] = swh[cur][nc][tig];
            bh[j][1] = swh[cur][nc][4 + tig];
            bl[j][0] = swl[cur][nc][tig];
            bl[j][1] = swl[cur][nc][4 + tig];
        }
#pragma unroll
        for (int j = 0; j < 4; j++) {
            mma_bf16(acc[j], ah, bh[j]);
            mma_bf16(acc[j], al, bh[j]);
            mma_bf16(acc[j], ah, bl[j]);
        }
        if (t < 31) {
            int nxt = cur ^ 1;
            float h0 = bf16_round(rx.x), h1 = bf16_round(rx.y);
            sxh[nxt][xrow][xp] = pack_bf16(rx.x, rx.y);
            sxl[nxt][xrow][xp] = pack_bf16(rx.x - h0, rx.y - h1);
            *reinterpret_cast<uint4*>(wsm + nxt * 1536 + wrow * 12 + wseg) = rw;
            __syncthreads();
            cur = nxt;
        }
    }

    {
        int prow = p0 + m_base + grp;
#pragma unroll
        for (int j = 0; j < 4; j++) {
            int col = n_base + j * 8 + 2 * tig;
            *reinterpret_cast<float2*>(&g_y[prow * 128 + col]) =
                make_float2(acc[j][0], acc[j][1]);
            *reinterpret_cast<float2*>(&g_y[(prow + 8) * 128 + col]) =
                make_float2(acc[j][2], acc[j][3]);
        }
    }
}

// ---------------------------------------------------------------------------
// kB: gather (max/min + sum/sumsq) + last-block BN1 finalize. grid=256, 256thr
// ---------------------------------------------------------------------------
__global__ void __launch_bounds__(256) kB_gather(const int* __restrict__ idx,
                                                 const float* __restrict__ gamma1,
                                                 const float* __restrict__ beta1) {
    __shared__ int   sidx[640];
    __shared__ float red[2][256];
    __shared__ float tot2[256];
    __shared__ bool  islast;

    int tid = threadIdx.x;
    int pbase = blockIdx.x * 32;
    for (int i = tid; i < 640; i += 256) sidx[i] = idx[pbase * 20 + i];
    __syncthreads();

    int m = tid & 63, slot = tid >> 6;
    float fs = 0.f, fq = 0.f;
#pragma unroll
    for (int i = 0; i < 8; i++) {
        int pl = slot * 8 + i;
        int p = pbase + pl;
        float y2 = g_y[p * 128 + 64 + m];
        int rowb = (p & ~1023) * 128;
        const int* ip = &sidx[pl * 20];
        float vmax = -1e30f, vmin = 1e30f;
#pragma unroll
        for (int k = 0; k < 20; k++) {
            float v = g_y[rowb + ip[k] * 128 + m] + y2;
            fs += v;
            fq += v * v;
            vmax = fmaxf(vmax, v);
            vmin = fminf(vmin, v);
        }
        g_hmax[p * 64 + m] = vmax;
        g_hmin[p * 64 + m] = vmin;
    }
    red[0][tid] = fs;
    red[1][tid] = fq;
    __syncthreads();
    if (tid < 64) {
        float s = red[0][tid] + red[0][tid + 64] + red[0][tid + 128] + red[0][tid + 192];
        float q = red[1][tid] + red[1][tid + 64] + red[1][tid + 128] + red[1][tid + 192];
        g_part1[tid * 256 + blockIdx.x] = s;
        g_part1[(64 + tid) * 256 + blockIdx.x] = q;
    }
    __threadfence();
    __syncthreads();
    if (tid == 0) {
        int old = atomicAdd(&g_cntB, 1);
        islast = (old == 255);
    }
    __syncthreads();
    if (!islast) return;
    __threadfence();

    {
        int col = tid & 127, half = tid >> 7;
        const float4* p4 = reinterpret_cast<const float4*>(&g_part1[col * 256 + half * 128]);
        float s = 0.f;
#pragma unroll 8
        for (int r = 0; r < 32; r++) {
            float4 v = p4[r];
            s += v.x + v.y + v.z + v.w;
        }
        red[0][tid] = s;
    }
    __syncthreads();
    if (tid < 128) tot2[tid] = red[0][tid] + red[0][tid + 128];
    __syncthreads();
    if (tid < 64) {
        float inv = 1.f / (float)CNT1;
        float mu = tot2[tid] * inv;
        float var = tot2[64 + tid] * inv - mu * mu;
        float sc = gamma1[tid] * rsqrtf(var + EPS);
        g_bn1[tid] = sc;
        g_bn1[64 + tid] = beta1[tid] - mu * sc;
        if (tid == 0) g_cntB = 0;
    }
}

// ---------------------------------------------------------------------------
// kC: pure bf16 GEMM2 + cheap register-stats epilogue (shfl + partial store,
// NO fence/atomic/tail). Tile 64p x 128d, 256 thr, grid (4,128).
// W2 chunks staged via coalesced uint4, double-buffered. Stores raw h2.
// Each warp writes its own partial-slot row: slot = by*2 + (w>>2).
// ---------------------------------------------------------------------------
__global__ void __launch_bounds__(256) kC_gemm2(float* __restrict__ out) {
    __shared__ uint32_t svh[64][36], svl[64][36];         // activations [p][mpair]
    __shared__ uint32_t sbh[2][128][12], sbl[2][128][12]; // W2 chunk [d][kpair]
    __shared__ float sbn[128];

    int tid = threadIdx.x;
    int lane = tid & 31, w = tid >> 5;
    int grp = lane >> 2, tig = lane & 3;
    int m_base = (w >> 2) * 32;     // p-offset: 0 or 32
    int n_base = (w & 3) * 32;      // d-offset: 0,32,64,96
    int d0 = blockIdx.x * 128;
    int p0 = blockIdx.y * 64;

    int wrow = tid >> 1;            // 0..127
    int whalf = (tid & 1) * 4;      // word 0 or 4

    if (tid < 128) sbn[tid] = g_bn1[tid];
    __syncthreads();

    uint4 rh = *reinterpret_cast<const uint4*>(&g_W2h[(d0 + wrow) * 32 + whalf]);
    uint4 rl = *reinterpret_cast<const uint4*>(&g_W2l[(d0 + wrow) * 32 + whalf]);
    *reinterpret_cast<uint4*>(&sbh[0][wrow][whalf]) = rh;
    *reinterpret_cast<uint4*>(&sbl[0][wrow][whalf]) = rl;

#pragma unroll
    for (int i = 0; i < 8; i++) {
        int e = tid + i * 256;
        int pt = e >> 5, mp = e & 31;
        int m0 = 2 * mp;
        float sc0 = sbn[m0], bi0 = sbn[64 + m0];
        float sc1 = sbn[m0 + 1], bi1 = sbn[64 + m0 + 1];
        const float* s0 = (sc0 >= 0.f) ? g_hmax : g_hmin;
        const float* s1 = (sc1 >= 0.f) ? g_hmax : g_hmin;
        float h0 = s0[(p0 + pt) * 64 + m0];
        float h1 = s1[(p0 + pt) * 64 + m0 + 1];
        float v0 = sc0 * h0 + bi0;
        float v1 = sc1 * h1 + bi1;
        v0 = fmaxf(v0, 0.2f * v0);
        v1 = fmaxf(v1, 0.2f * v1);
        float r0 = bf16_round(v0), r1 = bf16_round(v1);
        svh[pt][mp] = pack_bf16(v0, v1);
        svl[pt][mp] = pack_bf16(v0 - r0, v1 - r1);
    }
    __syncthreads();

    float acc[2][4][4];
#pragma unroll
    for (int r = 0; r < 2; r++)
#pragma unroll
        for (int j = 0; j < 4; j++)
#pragma unroll
            for (int q = 0; q < 4; q++) acc[r][j][q] = 0.f;

    int cur = 0;
    for (int ch = 0; ch < 4; ch++) {
        if (ch < 3) {
            int kb = (ch + 1) * 8;
            rh = *reinterpret_cast<const uint4*>(&g_W2h[(d0 + wrow) * 32 + kb + whalf]);
            rl = *reinterpret_cast<const uint4*>(&g_W2l[(d0 + wrow) * 32 + kb + whalf]);
        }
        int kb = ch * 8;
        uint32_t ah[2][4], al[2][4], bh[4][2], bl[4][2];
#pragma unroll
        for (int r = 0; r < 2; r++) {
            int mr = m_base + r * 16;
            ah[r][0] = svh[mr + grp][kb + tig];
            ah[r][1] = svh[mr + grp + 8][kb + tig];
            ah[r][2] = svh[mr + grp][kb + 4 + tig];
            ah[r][3] = svh[mr + grp + 8][kb + 4 + tig];
            al[r][0] = svl[mr + grp][kb + tig];
            al[r][1] = svl[mr + grp + 8][kb + tig];
            al[r][2] = svl[mr + grp][kb + 4 + tig];
            al[r][3] = svl[mr + grp + 8][kb + 4 + tig];
        }
#pragma unroll
        for (int j = 0; j < 4; j++) {
            int nc = n_base + j * 8 + grp;
            bh[j][0] = sbh[cur][nc][tig];
            bh[j][1] = sbh[cur][nc][4 + tig];
            bl[j][0] = sbl[cur][nc][tig];
            bl[j][1] = sbl[cur][nc][4 + tig];
        }
#pragma unroll
        for (int r = 0; r < 2; r++)
#pragma unroll
            for (int j = 0; j < 4; j++) {
                mma_bf16(acc[r][j], ah[r], bh[j]);
                mma_bf16(acc[r][j], al[r], bh[j]);
                mma_bf16(acc[r][j], ah[r], bl[j]);
            }
        if (ch < 3) {
            int nxt = cur ^ 1;
            *reinterpret_cast<uint4*>(&sbh[nxt][wrow][whalf]) = rh;
            *reinterpret_cast<uint4*>(&sbl[nxt][wrow][whalf]) = rl;
            __syncthreads();
            cur = nxt;
        }
    }

    // store raw h2 to out
#pragma unroll
    for (int r = 0; r < 2; r++) {
        int prow = p0 + m_base + r * 16 + grp;
#pragma unroll
        for (int j = 0; j < 4; j++) {
            int col = d0 + n_base + j * 8 + 2 * tig;
            *reinterpret_cast<float2*>(&out[prow * 512 + col]) =
                make_float2(acc[r][j][0], acc[r][j][1]);
            *reinterpret_cast<float2*>(&out[(prow + 8) * 512 + col]) =
                make_float2(acc[r][j][2], acc[r][j][3]);
        }
    }

    // cheap stats epilogue: per-warp shfl reduce + 8 partial stores (lanes 0-3)
    {
        float ts[8], tq[8];
#pragma unroll
        for (int i = 0; i < 8; i++) { ts[i] = 0.f; tq[i] = 0.f; }
#pragma unroll
        for (int r = 0; r < 2; r++)
#pragma unroll
            for (int j = 0; j < 4; j++)
#pragma unroll
                for (int q = 0; q < 2; q++) {
                    float a0 = acc[r][j][q], a1 = acc[r][j][2 + q];
                    ts[j * 2 + q] += a0 + a1;
                    tq[j * 2 + q] += a0 * a0 + a1 * a1;
                }
#pragma unroll
        for (int i = 0; i < 8; i++) {
#pragma unroll
            for (int off = 4; off < 32; off <<= 1) {
                ts[i] += __shfl_xor_sync(0xffffffffu, ts[i], off);
                tq[i] += __shfl_xor_sync(0xffffffffu, tq[i], off);
            }
        }
        if (lane < 4) {
            int slot = blockIdx.y * 2 + (w >> 2);   // 0..255, unique per warp-half
#pragma unroll
            for (int j = 0; j < 4; j++)
#pragma unroll
                for (int q = 0; q < 2; q++) {
                    int col = d0 + n_base + j * 8 + 2 * lane + q;
                    g_p2s[col * 256 + slot] = ts[j * 2 + q];
                    g_p2q[col * 256 + slot] = tq[j * 2 + q];
                }
        }
    }
}

// ---------------------------------------------------------------------------
// kD1: finalize BN2 from partials. 2 blocks x 256 thr, one column per thread,
// 64 contiguous uint4 loads per array. Kernel boundary = ordering.
// ---------------------------------------------------------------------------
__global__ void __launch_bounds__(256) kD1_fin(const float* __restrict__ gamma2,
                                               const float* __restrict__ beta2) {
    int col = blockIdx.x * 256 + threadIdx.x;   // 0..511
    const float4* p4s = reinterpret_cast<const float4*>(&g_p2s[col * 256]);
    const float4* p4q = reinterpret_cast<const float4*>(&g_p2q[col * 256]);
    float s = 0.f, q = 0.f;
#pragma unroll 8
    for (int r = 0; r < 64; r++) {
        float4 a = p4s[r];
        float4 b = p4q[r];
        s += a.x + a.y + a.z + a.w;
        q += b.x + b.y + b.z + b.w;
    }
    float inv = 1.f / (float)CNT2;
    float mu = s * inv;
    float var = q * inv - mu * mu;
    float sc = gamma2[col] * rsqrtf(var + EPS);
    g_bn2[col] = sc;
    g_bn2[512 + col] = beta2[col] - mu * sc;
}

// ---------------------------------------------------------------------------
// kD2: in-place affine + leaky on out. float4 data + float4 bn2 table loads.
// ---------------------------------------------------------------------------
__global__ void __launch_bounds__(512) kD2_final(float* __restrict__ out) {
    int i = blockIdx.x * 512 + threadIdx.x;   // float4 index, 1048576 total
    float4 v = reinterpret_cast<float4*>(out)[i];
    int d = (i * 4) & 511;
    float4 sc = *reinterpret_cast<const float4*>(&g_bn2[d]);
    float4 bi = *reinterpret_cast<const float4*>(&g_bn2[512 + d]);
    float t0 = sc.x * v.x + bi.x;
    float t1 = sc.y * v.y + bi.y;
    float t2 = sc.z * v.z + bi.z;
    float t3 = sc.w * v.w + bi.w;
    v.x = fmaxf(t0, 0.2f * t0);
    v.y = fmaxf(t1, 0.2f * t1);
    v.z = fmaxf(t2, 0.2f * t2);
    v.w = fmaxf(t3, 0.2f * t3);
    reinterpret_cast<float4*>(out)[i] = v;
}

// ---------------------------------------------------------------------------
extern "C" void kernel_launch(void* const* d_in, const int* in_sizes, int n_in,
                              void* d_out, int out_size) {
    const float* x      = (const float*)d_in[0];
    const int*   idx    = (const int*)  d_in[1];
    const float* W1     = (const float*)d_in[2];
    const float* gamma1 = (const float*)d_in[3];
    const float* beta1  = (const float*)d_in[4];
    const float* W2     = (const float*)d_in[5];
    const float* gamma2 = (const float*)d_in[6];
    const float* beta2  = (const float*)d_in[7];
    float* out = (float*)d_out;

    k0_prepw<<<192, 256>>>(W1, W2);
    kA_gemm1<<<128, 512>>>(x);
    kB_gather<<<256, 256>>>(idx, gamma1, beta1);
    kC_gemm2<<<dim3(4, 128), 256>>>(out);
    kD1_fin<<<2, 256>>>(gamma2, beta2);
    kD2_final<<<2048, 512>>>(out);
}

// round 16
// speedup vs baseline: 1.2843x; 1.0227x over previous
#include <cuda_runtime.h>
#include <cuda_bf16.h>
#include <cstdint>

#define Bb   8
#define Nn   1024
#define Cc   512
#define Kk   20
#define Mm   64
#define Pp   (Bb * Nn)        // 8192 points
#define CNT1 (Pp * Kk)        // 163840 samples for BN1
#define CNT2 Pp               // 8192 samples for BN2
#define EPS  1e-5f

// Scratch (no cudaMalloc allowed)
__device__ uint32_t g_W1h[128 * 256];   // folded W1' hi, packed bf16 pairs [n][kpair]
__device__ uint32_t g_W1l[128 * 256];   // folded W1' lo
__device__ uint32_t g_W2h[512 * 32];    // W2 hi, packed bf16 pairs [d][mpair]
__device__ uint32_t g_W2l[512 * 32];    // W2 lo
__device__ float g_yp0[Pp * 128];       // K-half 0 partial
__device__ float g_yp1[Pp * 128];       // K-half 1 partial
__device__ float g_y[Pp * 128];         // per-point y1(0:64) | y2(64:128)
__device__ float g_hmax[Pp * 64];
__device__ float g_hmin[Pp * 64];
__device__ float g_part1[128 * 256];    // transposed: [col(sum64|sq64)][block 256]
__device__ float g_bn1[128];            // scale(64) | bias(64)
__device__ float g_p2s[512 * 256];      // transposed: [col][slot 256]
__device__ float g_p2q[512 * 256];
__device__ float g_bn2[1024];           // scale(512) | bias(512)
__device__ int   g_cntB = 0;

__device__ __forceinline__ void mma_bf16(float* d, const uint32_t* a, const uint32_t* b) {
    asm volatile(
        "mma.sync.aligned.m16n8k16.row.col.f32.bf16.bf16.f32 "
        "{%0,%1,%2,%3}, {%4,%5,%6,%7}, {%8,%9}, {%0,%1,%2,%3};"
        : "+f"(d[0]), "+f"(d[1]), "+f"(d[2]), "+f"(d[3])
        : "r"(a[0]), "r"(a[1]), "r"(a[2]), "r"(a[3]),
          "r"(b[0]), "r"(b[1]));
}

__device__ __forceinline__ uint32_t pack_bf16(float a, float b) {
    __nv_bfloat162 t = __floats2bfloat162_rn(a, b);
    return *reinterpret_cast<uint32_t*>(&t);
}

__device__ __forceinline__ float bf16_round(float v) {
    return __bfloat162float(__float2bfloat16_rn(v));
}

// ---------------------------------------------------------------------------
// k0: prep W1' (fold + bf16 hi/lo pairs) and W2 (bf16 hi/lo pairs). grid=192
// ---------------------------------------------------------------------------
__global__ void k0_prepw(const float* __restrict__ W1, const float* __restrict__ W2) {
    int i = blockIdx.x * 256 + threadIdx.x;      // 0..49151
    if (i < 32768) {
        int n = i >> 8, kp = i & 255;
        int c = kp * 2;
        float v0, v1;
        if (n < 64) {
            float2 a = *reinterpret_cast<const float2*>(&W1[n * 1024 + c]);
            v0 = a.x; v1 = a.y;
        } else {
            int m = n - 64;
            float2 a = *reinterpret_cast<const float2*>(&W1[m * 1024 + c]);
            float2 b = *reinterpret_cast<const float2*>(&W1[m * 1024 + 512 + c]);
            v0 = b.x - a.x; v1 = b.y - a.y;
        }
        float h0 = bf16_round(v0), h1 = bf16_round(v1);
        g_W1h[i] = pack_bf16(v0, v1);
        g_W1l[i] = pack_bf16(v0 - h0, v1 - h1);
    } else {
        int j = i - 32768;                       // 0..16383
        int d = j >> 5, mp = j & 31;
        float2 a = *reinterpret_cast<const float2*>(&W2[d * 64 + mp * 2]);
        float h0 = bf16_round(a.x), h1 = bf16_round(a.y);
        g_W2h[j] = pack_bf16(a.x, a.y);
        g_W2l[j] = pack_bf16(a.x - h0, a.y - h1);
    }
}

// ---------------------------------------------------------------------------
// kA: GEMM1 K-split: y_part[kh] = x[:, kh*256:(kh+1)*256] @ W1'[:, khalf]^T.
// Tile 64p x 128n, 256 thr (8 warps: 2m x 4n, warp 32p x 32n), 16 iters,
// double-buffered, reg prefetch. grid (2,128) = 256 blocks, 2 blocks/SM.
// ---------------------------------------------------------------------------
__global__ void __launch_bounds__(256) kA_gemm1(const float* __restrict__ x) {
    __shared__ uint32_t sxh[2][64][12], sxl[2][64][12];
    __shared__ uint32_t swh[2][128][12], swl[2][128][12];

    int tid = threadIdx.x;
    int lane = tid & 31, w = tid >> 5;
    int grp = lane >> 2, tig = lane & 3;
    int m_base = (w >> 2) * 32;     // 0 or 32
    int n_base = (w & 3) * 32;      // 0,32,64,96
    int kh = blockIdx.x;            // K-half 0/1
    int p0 = blockIdx.y * 64;
    int kf0 = kh * 256;             // float offset base
    int kp0 = kh * 128;             // pair offset base

    float* dst = kh ? g_yp1 : g_yp0;

    int xrow = tid >> 2;            // 0..63
    int xc = tid & 3;               // float4 seg -> pairs 2xc, 2xc+1
    int wrow = tid >> 1;            // 0..127
    int wseg = (tid & 1) * 4;       // pair 0 or 4

    float acc[2][4][4];
#pragma unroll
    for (int r = 0; r < 2; r++)
#pragma unroll
        for (int j = 0; j < 4; j++)
#pragma unroll
            for (int q = 0; q < 4; q++) acc[r][j][q] = 0.f;

    float4 rx;
    uint4 rwh, rwl;
    rx  = *reinterpret_cast<const float4*>(&x[(p0 + xrow) * 512 + kf0 + 4 * xc]);
    rwh = *reinterpret_cast<const uint4*>(&g_W1h[wrow * 256 + kp0 + wseg]);
    rwl = *reinterpret_cast<const uint4*>(&g_W1l[wrow * 256 + kp0 + wseg]);
    {
        float h0 = bf16_round(rx.x), h1 = bf16_round(rx.y);
        float h2 = bf16_round(rx.z), h3 = bf16_round(rx.w);
        sxh[0][xrow][2 * xc]     = pack_bf16(rx.x, rx.y);
        sxh[0][xrow][2 * xc + 1] = pack_bf16(rx.z, rx.w);
        sxl[0][xrow][2 * xc]     = pack_bf16(rx.x - h0, rx.y - h1);
        sxl[0][xrow][2 * xc + 1] = pack_bf16(rx.z - h2, rx.w - h3);
        *reinterpret_cast<uint4*>(&swh[0][wrow][wseg]) = rwh;
        *reinterpret_cast<uint4*>(&swl[0][wrow][wseg]) = rwl;
    }
    __syncthreads();

    int cur = 0;
    for (int t = 0; t < 16; t++) {
        if (t < 15) {
            int kb = kf0 + (t + 1) * 16;
            rx  = *reinterpret_cast<const float4*>(&x[(p0 + xrow) * 512 + kb + 4 * xc]);
            rwh = *reinterpret_cast<const uint4*>(&g_W1h[wrow * 256 + kp0 + (t + 1) * 8 + wseg]);
            rwl = *reinterpret_cast<const uint4*>(&g_W1l[wrow * 256 + kp0 + (t + 1) * 8 + wseg]);
        }
        uint32_t ah[2][4], al[2][4], bh[4][2], bl[4][2];
#pragma unroll
        for (int r = 0; r < 2; r++) {
            int mr = m_base + r * 16;
            ah[r][0] = sxh[cur][mr + grp][tig];
            ah[r][1] = sxh[cur][mr + grp + 8][tig];
            ah[r][2] = sxh[cur][mr + grp][4 + tig];
            ah[r][3] = sxh[cur][mr + grp + 8][4 + tig];
            al[r][0] = sxl[cur][mr + grp][tig];
            al[r][1] = sxl[cur][mr + grp + 8][tig];
            al[r][2] = sxl[cur][mr + grp][4 + tig];
            al[r][3] = sxl[cur][mr + grp + 8][4 + tig];
        }
#pragma unroll
        for (int j = 0; j < 4; j++) {
            int nc = n_base + j * 8 + grp;
            bh[j][0] = swh[cur][nc][tig];
            bh[j][1] = swh[cur][nc][4 + tig];
            bl[j][0] = swl[cur][nc][tig];
            bl[j][1] = swl[cur][nc][4 + tig];
        }
#pragma unroll
        for (int r = 0; r < 2; r++)
#pragma unroll
            for (int j = 0; j < 4; j++) {
                mma_bf16(acc[r][j], ah[r], bh[j]);
                mma_bf16(acc[r][j], al[r], bh[j]);
                mma_bf16(acc[r][j], ah[r], bl[j]);
            }
        if (t < 15) {
            int nxt = cur ^ 1;
            float h0 = bf16_round(rx.x), h1 = bf16_round(rx.y);
            float h2 = bf16_round(rx.z), h3 = bf16_round(rx.w);
            sxh[nxt][xrow][2 * xc]     = pack_bf16(rx.x, rx.y);
            sxh[nxt][xrow][2 * xc + 1] = pack_bf16(rx.z, rx.w);
            sxl[nxt][xrow][2 * xc]     = pack_bf16(rx.x - h0, rx.y - h1);
            sxl[nxt][xrow][2 * xc + 1] = pack_bf16(rx.z - h2, rx.w - h3);
            *reinterpret_cast<uint4*>(&swh[nxt][wrow][wseg]) = rwh;
            *reinterpret_cast<uint4*>(&swl[nxt][wrow][wseg]) = rwl;
            __syncthreads();
            cur = nxt;
        }
    }

#pragma unroll
    for (int r = 0; r < 2; r++) {
        int prow = p0 + m_base + r * 16 + grp;
#pragma unroll
        for (int j = 0; j < 4; j++) {
            int col = n_base + j * 8 + 2 * tig;
            *reinterpret_cast<float2*>(&dst[prow * 128 + col]) =
                make_float2(acc[r][j][0], acc[r][j][1]);
            *reinterpret_cast<float2*>(&dst[(prow + 8) * 128 + col]) =
                make_float2(acc[r][j][2], acc[r][j][3]);
        }
    }
}

// ---------------------------------------------------------------------------
// kA2: y = yp0 + yp1 (float4 streamed)
// ---------------------------------------------------------------------------
__global__ void __launch_bounds__(512) kA2_add(int dummy) {
    int i = blockIdx.x * 512 + threadIdx.x;   // float4 index, 262144 total
    float4 a = reinterpret_cast<const float4*>(g_yp0)[i];
    float4 b = reinterpret_cast<const float4*>(g_yp1)[i];
    a.x += b.x; a.y += b.y; a.z += b.z; a.w += b.w;
    reinterpret_cast<float4*>(g_y)[i] = a;
}

// ---------------------------------------------------------------------------
// kB: gather (max/min + sum/sumsq) + last-block BN1 finalize. grid=256, 256thr
// ---------------------------------------------------------------------------
__global__ void __launch_bounds__(256) kB_gather(const int* __restrict__ idx,
                                                 const float* __restrict__ gamma1,
                                                 const float* __restrict__ beta1) {
    __shared__ int   sidx[640];
    __shared__ float red[2][256];
    __shared__ float tot2[256];
    __shared__ bool  islast;

    int tid = threadIdx.x;
    int pbase = blockIdx.x * 32;
    for (int i = tid; i < 640; i += 256) sidx[i] = idx[pbase * 20 + i];
    __syncthreads();

    int m = tid & 63, slot = tid >> 6;
    float fs = 0.f, fq = 0.f;
#pragma unroll
    for (int i = 0; i < 8; i++) {
        int pl = slot * 8 + i;
        int p = pbase + pl;
        float y2 = g_y[p * 128 + 64 + m];
        int rowb = (p & ~1023) * 128;
        const int* ip = &sidx[pl * 20];
        float vmax = -1e30f, vmin = 1e30f;
#pragma unroll
        for (int k = 0; k < 20; k++) {
            float v = g_y[rowb + ip[k] * 128 + m] + y2;
            fs += v;
            fq += v * v;
            vmax = fmaxf(vmax, v);
            vmin = fminf(vmin, v);
        }
        g_hmax[p * 64 + m] = vmax;
        g_hmin[p * 64 + m] = vmin;
    }
    red[0][tid] = fs;
    red[1][tid] = fq;
    __syncthreads();
    if (tid < 64) {
        float s = red[0][tid] + red[0][tid + 64] + red[0][tid + 128] + red[0][tid + 192];
        float q = red[1][tid] + red[1][tid + 64] + red[1][tid + 128] + red[1][tid + 192];
        g_part1[tid * 256 + blockIdx.x] = s;
        g_part1[(64 + tid) * 256 + blockIdx.x] = q;
    }
    __threadfence();
    __syncthreads();
    if (tid == 0) {
        int old = atomicAdd(&g_cntB, 1);
        islast = (old == 255);
    }
    __syncthreads();
    if (!islast) return;
    __threadfence();

    {
        int col = tid & 127, half = tid >> 7;
        const float4* p4 = reinterpret_cast<const float4*>(&g_part1[col * 256 + half * 128]);
        float s = 0.f;
#pragma unroll 8
        for (int r = 0; r < 32; r++) {
            float4 v = p4[r];
            s += v.x + v.y + v.z + v.w;
        }
        red[0][tid] = s;
    }
    __syncthreads();
    if (tid < 128) tot2[tid] = red[0][tid] + red[0][tid + 128];
    __syncthreads();
    if (tid < 64) {
        float inv = 1.f / (float)CNT1;
        float mu = tot2[tid] * inv;
        float var = tot2[64 + tid] * inv - mu * mu;
        float sc = gamma1[tid] * rsqrtf(var + EPS);
        g_bn1[tid] = sc;
        g_bn1[64 + tid] = beta1[tid] - mu * sc;
        if (tid == 0) g_cntB = 0;
    }
}

// ---------------------------------------------------------------------------
// kC: pure bf16 GEMM2 + cheap register-stats epilogue (shfl + partial store,
// NO fence/atomic/tail). Tile 64p x 128d, 256 thr, grid (4,128).
// ---------------------------------------------------------------------------
__global__ void __launch_bounds__(256) kC_gemm2(float* __restrict__ out) {
    __shared__ uint32_t svh[64][36], svl[64][36];
    __shared__ uint32_t sbh[2][128][12], sbl[2][128][12];
    __shared__ float sbn[128];

    int tid = threadIdx.x;
    int lane = tid & 31, w = tid >> 5;
    int grp = lane >> 2, tig = lane & 3;
    int m_base = (w >> 2) * 32;
    int n_base = (w & 3) * 32;
    int d0 = blockIdx.x * 128;
    int p0 = blockIdx.y * 64;

    int wrow = tid >> 1;
    int whalf = (tid & 1) * 4;

    if (tid < 128) sbn[tid] = g_bn1[tid];
    __syncthreads();

    uint4 rh = *reinterpret_cast<const uint4*>(&g_W2h[(d0 + wrow) * 32 + whalf]);
    uint4 rl = *reinterpret_cast<const uint4*>(&g_W2l[(d0 + wrow) * 32 + whalf]);
    *reinterpret_cast<uint4*>(&sbh[0][wrow][whalf]) = rh;
    *reinterpret_cast<uint4*>(&sbl[0][wrow][whalf]) = rl;

#pragma unroll
    for (int i = 0; i < 8; i++) {
        int e = tid + i * 256;
        int pt = e >> 5, mp = e & 31;
        int m0 = 2 * mp;
        float sc0 = sbn[m0], bi0 = sbn[64 + m0];
        float sc1 = sbn[m0 + 1], bi1 = sbn[64 + m0 + 1];
        const float* s0 = (sc0 >= 0.f) ? g_hmax : g_hmin;
        const float* s1 = (sc1 >= 0.f) ? g_hmax : g_hmin;
        float h0 = s0[(p0 + pt) * 64 + m0];
        float h1 = s1[(p0 + pt) * 64 + m0 + 1];
        float v0 = sc0 * h0 + bi0;
        float v1 = sc1 * h1 + bi1;
        v0 = fmaxf(v0, 0.2f * v0);
        v1 = fmaxf(v1, 0.2f * v1);
        float r0 = bf16_round(v0), r1 = bf16_round(v1);
        svh[pt][mp] = pack_bf16(v0, v1);
        svl[pt][mp] = pack_bf16(v0 - r0, v1 - r1);
    }
    __syncthreads();

    float acc[2][4][4];
#pragma unroll
    for (int r = 0; r < 2; r++)
#pragma unroll
        for (int j = 0; j < 4; j++)
#pragma unroll
            for (int q = 0; q < 4; q++) acc[r][j][q] = 0.f;

    int cur = 0;
    for (int ch = 0; ch < 4; ch++) {
        if (ch < 3) {
            int kb = (ch + 1) * 8;
            rh = *reinterpret_cast<const uint4*>(&g_W2h[(d0 + wrow) * 32 + kb + whalf]);
            rl = *reinterpret_cast<const uint4*>(&g_W2l[(d0 + wrow) * 32 + kb + whalf]);
        }
        int kb = ch * 8;
        uint32_t ah[2][4], al[2][4], bh[4][2], bl[4][2];
#pragma unroll
        for (int r = 0; r < 2; r++) {
            int mr = m_base + r * 16;
            ah[r][0] = svh[mr + grp][kb + tig];
            ah[r][1] = svh[mr + grp + 8][kb + tig];
            ah[r][2] = svh[mr + grp][kb + 4 + tig];
            ah[r][3] = svh[mr + grp + 8][kb + 4 + tig];
            al[r][0] = svl[mr + grp][kb + tig];
            al[r][1] = svl[mr + grp + 8][kb + tig];
            al[r][2] = svl[mr + grp][kb + 4 + tig];
            al[r][3] = svl[mr + grp + 8][kb + 4 + tig];
        }
#pragma unroll
        for (int j = 0; j < 4; j++) {
            int nc = n_base + j * 8 + grp;
            bh[j][0] = sbh[cur][nc][tig];
            bh[j][1] = sbh[cur][nc][4 + tig];
            bl[j][0] = sbl[cur][nc][tig];
            bl[j][1] = sbl[cur][nc][4 + tig];
        }
#pragma unroll
        for (int r = 0; r < 2; r++)
#pragma unroll
            for (int j = 0; j < 4; j++) {
                mma_bf16(acc[r][j], ah[r], bh[j]);
                mma_bf16(acc[r][j], al[r], bh[j]);
                mma_bf16(acc[r][j], ah[r], bl[j]);
            }
        if (ch < 3) {
            int nxt = cur ^ 1;
            *reinterpret_cast<uint4*>(&sbh[nxt][wrow][whalf]) = rh;
            *reinterpret_cast<uint4*>(&sbl[nxt][wrow][whalf]) = rl;
            __syncthreads();
            cur = nxt;
        }
    }

#pragma unroll
    for (int r = 0; r < 2; r++) {
        int prow = p0 + m_base + r * 16 + grp;
#pragma unroll
        for (int j = 0; j < 4; j++) {
            int col = d0 + n_base + j * 8 + 2 * tig;
            *reinterpret_cast<float2*>(&out[prow * 512 + col]) =
                make_float2(acc[r][j][0], acc[r][j][1]);
            *reinterpret_cast<float2*>(&out[(prow + 8) * 512 + col]) =
                make_float2(acc[r][j][2], acc[r][j][3]);
        }
    }

    // cheap stats epilogue
    {
        float ts[8], tq[8];
#pragma unroll
        for (int i = 0; i < 8; i++) { ts[i] = 0.f; tq[i] = 0.f; }
#pragma unroll
        for (int r = 0; r < 2; r++)
#pragma unroll
            for (int j = 0; j < 4; j++)
#pragma unroll
                for (int q = 0; q < 2; q++) {
                    float a0 = acc[r][j][q], a1 = acc[r][j][2 + q];
                    ts[j * 2 + q] += a0 + a1;
                    tq[j * 2 + q] += a0 * a0 + a1 * a1;
                }
#pragma unroll
        for (int i = 0; i < 8; i++) {
#pragma unroll
            for (int off = 4; off < 32; off <<= 1) {
                ts[i] += __shfl_xor_sync(0xffffffffu, ts[i], off);
                tq[i] += __shfl_xor_sync(0xffffffffu, tq[i], off);
            }
        }
        if (lane < 4) {
            int slot = blockIdx.y * 2 + (w >> 2);
#pragma unroll
            for (int j = 0; j < 4; j++)
#pragma unroll
                for (int q = 0; q < 2; q++) {
                    int col = d0 + n_base + j * 8 + 2 * lane + q;
                    g_p2s[col * 256 + slot] = ts[j * 2 + q];
                    g_p2q[col * 256 + slot] = tq[j * 2 + q];
                }
        }
    }
}

// ---------------------------------------------------------------------------
// kD1: finalize BN2 from partials. 2 blocks x 256 thr.
// ---------------------------------------------------------------------------
__global__ void __launch_bounds__(256) kD1_fin(const float* __restrict__ gamma2,
                                               const float* __restrict__ beta2) {
    int col = blockIdx.x * 256 + threadIdx.x;   // 0..511
    const float4* p4s = reinterpret_cast<const float4*>(&g_p2s[col * 256]);
    const float4* p4q = reinterpret_cast<const float4*>(&g_p2q[col * 256]);
    float s = 0.f, q = 0.f;
#pragma unroll 8
    for (int r = 0; r < 64; r++) {
        float4 a = p4s[r];
        float4 b = p4q[r];
        s += a.x + a.y + a.z + a.w;
        q += b.x + b.y + b.z + b.w;
    }
    float inv = 1.f / (float)CNT2;
    float mu = s * inv;
    float var = q * inv - mu * mu;
    float sc = gamma2[col] * rsqrtf(var + EPS);
    g_bn2[col] = sc;
    g_bn2[512 + col] = beta2[col] - mu * sc;
}

// ---------------------------------------------------------------------------
// kD2: in-place affine + leaky on out.
// ---------------------------------------------------------------------------
__global__ void __launch_bounds__(512) kD2_final(float* __restrict__ out) {
    int i = blockIdx.x * 512 + threadIdx.x;   // float4 index, 1048576 total
    float4 v = reinterpret_cast<float4*>(out)[i];
    int d = (i * 4) & 511;
    float4 sc = *reinterpret_cast<const float4*>(&g_bn2[d]);
    float4 bi = *reinterpret_cast<const float4*>(&g_bn2[512 + d]);
    float t0 = sc.x * v.x + bi.x;
    float t1 = sc.y * v.y + bi.y;
    float t2 = sc.z * v.z + bi.z;
    float t3 = sc.w * v.w + bi.w;
    v.x = fmaxf(t0, 0.2f * t0);
    v.y = fmaxf(t1, 0.2f * t1);
    v.z = fmaxf(t2, 0.2f * t2);
    v.w = fmaxf(t3, 0.2f * t3);
    reinterpret_cast<float4*>(out)[i] = v;
}

// ---------------------------------------------------------------------------
extern "C" void kernel_launch(void* const* d_in, const int* in_sizes, int n_in,
                              void* d_out, int out_size) {
    const float* x      = (const float*)d_in[0];
    const int*   idx    = (const int*)  d_in[1];
    const float* W1     = (const float*)d_in[2];
    const float* gamma1 = (const float*)d_in[3];
    const float* beta1  = (const float*)d_in[4];
    const float* W2     = (const float*)d_in[5];
    const float* gamma2 = (const float*)d_in[6];
    const float* beta2  = (const float*)d_in[7];
    float* out = (float*)d_out;

    k0_prepw<<<192, 256>>>(W1, W2);
    kA_gemm1<<<dim3(2, 128), 256>>>(x);
    kA2_add<<<512, 512>>>(0);
    kB_gather<<<256, 256>>>(idx, gamma1, beta1);
    kC_gemm2<<<dim3(4, 128), 256>>>(out);
    kD1_fin<<<2, 256>>>(gamma2, beta2);
    kD2_final<<<2048, 512>>>(out);
}